// round 13
// baseline (speedup 1.0000x reference)
#include <cuda_runtime.h>
#include <cstdint>

// FerroelectricBasisConv2d — GB300 sm_103a, round 13
// Split-sum decomposition: 256-thr blocks, 2 threads per output pixel
// (c 0-3 vs c 4-7), combine via smem. Doubles warp supply: 8 warps/SMSP.
// Hybrid gate unchanged (kkk==0 MUFU tanh; kkk==1,2 packed-f32x2 rational),
// u = k*x + 0.9kEc*(1 + g/9). 64-bit integer magic-rcp (one IADD, no unpack).

#define CIN     16
#define COUT    32
#define HW      32
#define NT      432
#define NPAIR   216
#define TILE_H  8
#define TILE_W  16
#define RG_H    10
#define RG_W    18
#define THREADS 256

typedef unsigned long long ull;

__device__ __forceinline__ float tanh_fast(float x) {
    float r; asm("tanh.approx.f32 %0, %1;" : "=f"(r) : "f"(x)); return r;
}
__device__ __forceinline__ ull f2_fma(ull a, ull b, ull c) {
    ull d; asm("fma.rn.f32x2 %0, %1, %2, %3;" : "=l"(d) : "l"(a), "l"(b), "l"(c)); return d;
}
__device__ __forceinline__ ull f2_mul(ull a, ull b) {
    ull d; asm("mul.rn.f32x2 %0, %1, %2;" : "=l"(d) : "l"(a), "l"(b)); return d;
}
__device__ __forceinline__ ull f2_add(ull a, ull b) {
    ull d; asm("add.rn.f32x2 %0, %1, %2;" : "=l"(d) : "l"(a), "l"(b)); return d;
}
__device__ __forceinline__ ull f2_pack(float lo, float hi) {
    ull d; asm("mov.b64 %0, {%1, %2};" : "=l"(d) : "f"(lo), "f"(hi)); return d;
}
__device__ __forceinline__ void f2_unpack(ull v, float& lo, float& hi) {
    asm("mov.b64 {%0, %1}, %2;" : "=f"(lo), "=f"(hi) : "l"(v));
}

// rational gate coefficients (|err| <= 8e-4 on [-4,4])
#define GA1 0.0837500f
#define GB1 0.4158160f
#define GB2 0.0066923f
// packed magic reciprocal seed: den lanes < 0x41340000 << 0x7EF127EA -> no borrow
#define MAGIC2 0x7EF127EA7EF127EAULL

__global__ __launch_bounds__(THREADS, 4)
void ferro_kernel(const float* __restrict__ x,
                  const float* __restrict__ k,
                  const float* __restrict__ Ec,
                  const float* __restrict__ Ps,
                  const float* __restrict__ bias,
                  const float* __restrict__ coef,
                  const float* __restrict__ out_bias,
                  float* __restrict__ out)
{
    __shared__ float2 fe[NPAIR];   // {5Ec_j, 5Ec_j+216}
    __shared__ float2 fk[NPAIR];   // {k0, k1}
    __shared__ float2 fb[NPAIR];   // {0.9kEc0, 0.9kEc1}
    __shared__ float2 fw[NPAIR];   // {Ps*coef0, Ps*coef1}
    __shared__ float  xs[CIN * RG_H * RG_W];
    __shared__ float  wsum[8];
    __shared__ float  psum[128];

    const int tid  = threadIdx.x;
    const int half = tid >> 7;        // 0: c 0-3 (+writes), 1: c 4-7
    const int pid  = tid & 127;       // pixel id within tile
    const int bx   = blockIdx.x;
    const int sub  = bx & 7;
    const int sy   = sub >> 1, sx = sub & 1;
    const int co   = (bx >> 3) & 31;
    const int b    = bx >> 8;
    const int oy0  = sy * TILE_H, ox0 = sx * TILE_W;

    const float* kp  = k    + co * NT;
    const float* ep  = Ec   + co * NT;
    const float* pp  = Ps   + co * NT;
    const float* bp  = bias + co * NT;
    const float* cp  = coef + co * NT;

    float part = 0.0f;
    for (int j = tid; j < NPAIR; j += THREADS) {
        int j1 = j + NPAIR;
        float k0 = kp[j],  e0 = ep[j],  k1 = kp[j1], e1 = ep[j1];
        fe[j] = make_float2(5.0f * e0, 5.0f * e1);
        fk[j] = make_float2(k0, k1);
        fb[j] = make_float2(0.9f * k0 * e0, 0.9f * k1 * e1);
        fw[j] = make_float2(pp[j] * cp[j], pp[j1] * cp[j1]);
        part += bp[j] * cp[j] + bp[j1] * cp[j1];
    }
    // warp shfl reduce of sum(bias*coef), 8 warps
    #pragma unroll
    for (int off = 16; off > 0; off >>= 1)
        part += __shfl_xor_sync(0xffffffffu, part, off);
    if ((tid & 31) == 0) wsum[tid >> 5] = part;

    for (int i = tid; i < CIN * RG_H * RG_W; i += THREADS) {
        int cin = i / (RG_H * RG_W);
        int rem = i - cin * (RG_H * RG_W);
        int r   = rem / RG_W;
        int c   = rem - r * RG_W;
        int gy  = oy0 - 1 + r;
        int gx  = ox0 - 1 + c;
        float v = 0.0f;
        if ((unsigned)gy < (unsigned)HW && (unsigned)gx < (unsigned)HW)
            v = x[((b * CIN + cin) * HW + gy) * HW + gx];
        xs[i] = v;
    }
    __syncthreads();

    const int ty = pid >> 4;
    const int tx = pid & 15;

    float acc0 = 0.0f;
    float acc1 = 0.0f;

    const ull* feu = reinterpret_cast<const ull*>(fe);
    const ull* fku = reinterpret_cast<const ull*>(fk);
    const ull* fbu = reinterpret_cast<const ull*>(fb);

    const ull ONE2  = f2_pack(1.0f, 1.0f);
    const ull A12   = f2_pack(GA1, GA1);
    const ull B12   = f2_pack(GB1, GB1);
    const ull B22   = f2_pack(GB2, GB2);
    const ull MTWO2 = f2_pack(-2.0f, -2.0f);
    const ull N9N2  = f2_pack(-0.111111111f, -0.111111111f);

    const int c0 = half * 4;
    for (int ci = 0; ci < 4; ++ci) {
        const int c = c0 + ci;
        const float* xb0 = xs + c * (RG_H * RG_W) + ty * RG_W + tx;
        const float* xb1 = xb0 + 8 * (RG_H * RG_W);
        const int jb = c * 27;
        #pragma unroll
        for (int kh = 0; kh < 3; ++kh) {
            #pragma unroll
            for (int kw = 0; kw < 3; ++kw) {
                const float xv0 = xb0[kh * RG_W + kw];
                const float xv1 = xb1[kh * RG_W + kw];
                const ull x2  = f2_pack(xv0, xv1);
                const ull fx2 = f2_pack(5.0f * xv0, 5.0f * xv1);
                const int tap = kh * 3 + kw;
                #pragma unroll
                for (int kkk = 0; kkk < 3; ++kkk) {
                    const int j = jb + kkk * 9 + tap;
                    float2 wv = fw[j];
                    if (kkk == 0) {
                        // MUFU gate branch
                        float2 ev = fe[j], kv = fk[j], bv = fb[j];
                        float g0 = tanh_fast(fmaf(5.0f, xv0, ev.x));
                        float g1 = tanh_fast(fmaf(5.0f, xv1, ev.y));
                        float m0 = fmaf(g0, 0.111111111f, 1.0f);
                        float m1 = fmaf(g1, 0.111111111f, 1.0f);
                        float u0 = fmaf(bv.x, m0, kv.x * xv0);
                        float u1 = fmaf(bv.y, m1, kv.y * xv1);
                        acc0 = fmaf(wv.x, tanh_fast(u0), acc0);
                        acc1 = fmaf(wv.y, tanh_fast(u1), acc1);
                    } else {
                        // packed rational gate branch
                        ull a2 = f2_add(fx2, feu[j]);
                        float al, ah; f2_unpack(a2, al, ah);
                        al = fminf(fmaxf(al, -4.0f), 4.0f);
                        ah = fminf(fmaxf(ah, -4.0f), 4.0f);
                        ull acl = f2_pack(al, ah);

                        ull t2   = f2_mul(acl, acl);
                        ull pp2  = f2_fma(t2, A12, ONE2);
                        ull num2 = f2_mul(acl, pp2);
                        ull q2   = f2_fma(t2, B22, B12);
                        ull d2   = f2_fma(t2, q2, ONE2);

                        ull r0 = MAGIC2 - d2;               // packed magic rcp seed (1 IADD)
                        ull m2 = f2_fma(d2, r0, MTWO2);     // d*r0 - 2
                        ull rn = f2_mul(r0, m2);            // -1/d

                        ull gn2  = f2_mul(num2, rn);        // -g
                        ull mom2 = f2_fma(gn2, N9N2, ONE2); // 1 + g/9
                        ull kx2  = f2_mul(fku[j], x2);
                        ull u2   = f2_fma(fbu[j], mom2, kx2);

                        float u0, u1; f2_unpack(u2, u0, u1);
                        acc0 = fmaf(wv.x, tanh_fast(u0), acc0);
                        acc1 = fmaf(wv.y, tanh_fast(u1), acc1);
                    }
                }
            }
        }
    }

    float partial = acc0 + acc1;
    if (half) psum[pid] = partial;
    __syncthreads();

    if (!half) {
        float base = wsum[0] + wsum[1] + wsum[2] + wsum[3]
                   + wsum[4] + wsum[5] + wsum[6] + wsum[7]
                   + __ldg(out_bias + co);
        const int oy = oy0 + ty, ox = ox0 + tx;
        out[((b * COUT + co) * HW + oy) * HW + ox] = base + partial + psum[pid];
    }
}

extern "C" void kernel_launch(void* const* d_in, const int* in_sizes, int n_in,
                              void* d_out, int out_size)
{
    const float* x        = (const float*)d_in[0];
    const float* k        = (const float*)d_in[1];
    const float* Ec       = (const float*)d_in[2];
    const float* Ps       = (const float*)d_in[3];
    const float* bias     = (const float*)d_in[4];
    const float* coef     = (const float*)d_in[5];
    const float* out_bias = (const float*)d_in[6];
    float* out = (float*)d_out;

    // 1024 blocks x 256 threads: 2 threads per output, 8192 warps total
    ferro_kernel<<<4 * 32 * 8, THREADS>>>(x, k, Ec, Ps, bias, coef, out_bias, out);
}

// round 14
// speedup vs baseline: 1.1824x; 1.1824x over previous
#include <cuda_runtime.h>
#include <cstdint>

// FerroelectricBasisConv2d — GB300 sm_103a, round 14
// r12 base (128 thr, 1 pixel-pair/thread) with:
//  - params merged into 2 float4 arrays -> 2x LDS.128 per pair (was 4x LDS.64)
//  - MUFU/rational gate split raised to 14/27 via parity of (kkk*9+tap)
// Model: T = max(MUFU 48.6k, issued/0.70 ~46k) -> ~26-30us.
//   gate g=tanh(5x+5Ec); u = k*x + 0.9kEc*(1+g/9); out += w*tanh(u)

#define CIN     16
#define COUT    32
#define HW      32
#define NT      432
#define NPAIR   216
#define TILE_H  8
#define TILE_W  16
#define RG_H    10
#define RG_W    18
#define THREADS 128

typedef unsigned long long ull;

__device__ __forceinline__ float tanh_fast(float x) {
    float r; asm("tanh.approx.f32 %0, %1;" : "=f"(r) : "f"(x)); return r;
}
__device__ __forceinline__ ull f2_fma(ull a, ull b, ull c) {
    ull d; asm("fma.rn.f32x2 %0, %1, %2, %3;" : "=l"(d) : "l"(a), "l"(b), "l"(c)); return d;
}
__device__ __forceinline__ ull f2_mul(ull a, ull b) {
    ull d; asm("mul.rn.f32x2 %0, %1, %2;" : "=l"(d) : "l"(a), "l"(b)); return d;
}
__device__ __forceinline__ ull f2_add(ull a, ull b) {
    ull d; asm("add.rn.f32x2 %0, %1, %2;" : "=l"(d) : "l"(a), "l"(b)); return d;
}
__device__ __forceinline__ ull f2_pack(float lo, float hi) {
    ull d; asm("mov.b64 %0, {%1, %2};" : "=l"(d) : "f"(lo), "f"(hi)); return d;
}
__device__ __forceinline__ void f2_unpack(ull v, float& lo, float& hi) {
    asm("mov.b64 {%0, %1}, %2;" : "=f"(lo), "=f"(hi) : "l"(v));
}

// rational gate coefficients (|err| <= 8e-4 on [-4,4])
#define GA1 0.0837500f
#define GB1 0.4158160f
#define GB2 0.0066923f
// packed magic rcp seed: den lane bits < 0x41340000 << 0x7EF127EA -> no borrow
#define MAGIC2 0x7EF127EA7EF127EAULL

__global__ __launch_bounds__(THREADS, 8)
void ferro_kernel(const float* __restrict__ x,
                  const float* __restrict__ k,
                  const float* __restrict__ Ec,
                  const float* __restrict__ Ps,
                  const float* __restrict__ bias,
                  const float* __restrict__ coef,
                  const float* __restrict__ out_bias,
                  float* __restrict__ out)
{
    __shared__ float4 fA[NPAIR];   // {5Ec0, 5Ec1, k0, k1}
    __shared__ float4 fB[NPAIR];   // {0.9kEc0, 0.9kEc1, w0, w1}
    __shared__ float  xs[CIN * RG_H * RG_W];
    __shared__ float  red[THREADS];

    const int tid = threadIdx.x;
    const int bx  = blockIdx.x;
    const int sub = bx & 7;
    const int sy  = sub >> 1, sx = sub & 1;
    const int co  = (bx >> 3) & 31;
    const int b   = bx >> 8;
    const int oy0 = sy * TILE_H, ox0 = sx * TILE_W;

    const float* kp  = k    + co * NT;
    const float* ep  = Ec   + co * NT;
    const float* pp  = Ps   + co * NT;
    const float* bp  = bias + co * NT;
    const float* cp  = coef + co * NT;

    float part = 0.0f;
    for (int j = tid; j < NPAIR; j += THREADS) {
        int j1 = j + NPAIR;
        float k0 = kp[j],  e0 = ep[j],  k1 = kp[j1], e1 = ep[j1];
        fA[j] = make_float4(5.0f * e0, 5.0f * e1, k0, k1);
        fB[j] = make_float4(0.9f * k0 * e0, 0.9f * k1 * e1,
                            pp[j] * cp[j], pp[j1] * cp[j1]);
        part += bp[j] * cp[j] + bp[j1] * cp[j1];
    }
    red[tid] = part;

    for (int i = tid; i < CIN * RG_H * RG_W; i += THREADS) {
        int cin = i / (RG_H * RG_W);
        int rem = i - cin * (RG_H * RG_W);
        int r   = rem / RG_W;
        int c   = rem - r * RG_W;
        int gy  = oy0 - 1 + r;
        int gx  = ox0 - 1 + c;
        float v = 0.0f;
        if ((unsigned)gy < (unsigned)HW && (unsigned)gx < (unsigned)HW)
            v = x[((b * CIN + cin) * HW + gy) * HW + gx];
        xs[i] = v;
    }
    __syncthreads();

    #pragma unroll
    for (int s = THREADS / 2; s > 0; s >>= 1) {
        if (tid < s) red[tid] += red[tid + s];
        __syncthreads();
    }

    const int ty = tid >> 4;
    const int tx = tid & 15;

    float acc0 = red[0] + __ldg(out_bias + co);
    float acc1 = 0.0f;

    const ull ONE2  = f2_pack(1.0f, 1.0f);
    const ull A12   = f2_pack(GA1, GA1);
    const ull B12   = f2_pack(GB1, GB1);
    const ull B22   = f2_pack(GB2, GB2);
    const ull MTWO2 = f2_pack(-2.0f, -2.0f);
    const ull N9N2  = f2_pack(-0.111111111f, -0.111111111f);

    for (int c = 0; c < 8; ++c) {
        const float* xb0 = xs + c * (RG_H * RG_W) + ty * RG_W + tx;
        const float* xb1 = xb0 + 8 * (RG_H * RG_W);
        const int jb = c * 27;
        #pragma unroll
        for (int kh = 0; kh < 3; ++kh) {
            #pragma unroll
            for (int kw = 0; kw < 3; ++kw) {
                const float xv0 = xb0[kh * RG_W + kw];
                const float xv1 = xb1[kh * RG_W + kw];
                const ull x2  = f2_pack(xv0, xv1);
                const ull fx2 = f2_pack(5.0f * xv0, 5.0f * xv1);
                const int tap = kh * 3 + kw;
                #pragma unroll
                for (int kkk = 0; kkk < 3; ++kkk) {
                    const int j = jb + kkk * 9 + tap;
                    float4 a = fA[j];     // {5Ec0,5Ec1,k0,k1}   LDS.128
                    float4 pb = fB[j];    // {b0,b1,w0,w1}        LDS.128
                    if (((kkk * 9 + tap) & 1) == 0) {
                        // MUFU gate branch (14 of 27 taps)
                        float g0 = tanh_fast(fmaf(5.0f, xv0, a.x));
                        float g1 = tanh_fast(fmaf(5.0f, xv1, a.y));
                        float m0 = fmaf(g0, 0.111111111f, 1.0f);
                        float m1 = fmaf(g1, 0.111111111f, 1.0f);
                        float u0 = fmaf(pb.x, m0, a.z * xv0);
                        float u1 = fmaf(pb.y, m1, a.w * xv1);
                        acc0 = fmaf(pb.z, tanh_fast(u0), acc0);
                        acc1 = fmaf(pb.w, tanh_fast(u1), acc1);
                    } else {
                        // packed rational gate branch (13 of 27 taps)
                        ull e2 = f2_pack(a.x, a.y);     // reg-pair alias of LDS.128
                        ull k2 = f2_pack(a.z, a.w);
                        ull b2 = f2_pack(pb.x, pb.y);

                        ull a2 = f2_add(fx2, e2);
                        float al, ah; f2_unpack(a2, al, ah);
                        al = fminf(fmaxf(al, -4.0f), 4.0f);
                        ah = fminf(fmaxf(ah, -4.0f), 4.0f);
                        ull acl = f2_pack(al, ah);

                        ull t2   = f2_mul(acl, acl);
                        ull pp2  = f2_fma(t2, A12, ONE2);
                        ull num2 = f2_mul(acl, pp2);
                        ull q2   = f2_fma(t2, B22, B12);
                        ull d2   = f2_fma(t2, q2, ONE2);

                        ull r0 = MAGIC2 - d2;               // packed magic seed
                        ull m2 = f2_fma(d2, r0, MTWO2);     // d*r0 - 2
                        ull rn = f2_mul(r0, m2);            // -1/d

                        ull gn2  = f2_mul(num2, rn);        // -g
                        ull mom2 = f2_fma(gn2, N9N2, ONE2); // 1 + g/9
                        ull kx2  = f2_mul(k2, x2);
                        ull u2   = f2_fma(b2, mom2, kx2);

                        float u0, u1; f2_unpack(u2, u0, u1);
                        acc0 = fmaf(pb.z, tanh_fast(u0), acc0);
                        acc1 = fmaf(pb.w, tanh_fast(u1), acc1);
                    }
                }
            }
        }
    }

    const int oy = oy0 + ty, ox = ox0 + tx;
    out[((b * COUT + co) * HW + oy) * HW + ox] = acc0 + acc1;
}

extern "C" void kernel_launch(void* const* d_in, const int* in_sizes, int n_in,
                              void* d_out, int out_size)
{
    const float* x        = (const float*)d_in[0];
    const float* k        = (const float*)d_in[1];
    const float* Ec       = (const float*)d_in[2];
    const float* Ps       = (const float*)d_in[3];
    const float* bias     = (const float*)d_in[4];
    const float* coef     = (const float*)d_in[5];
    const float* out_bias = (const float*)d_in[6];
    float* out = (float*)d_out;

    ferro_kernel<<<4 * 32 * 8, THREADS>>>(x, k, Ec, Ps, bias, coef, out_bias, out);
}